// round 16
// baseline (speedup 1.0000x reference)
#include <cuda_runtime.h>
#include <float.h>

// And_Convolution: out[n][s] = min_{k<16} ( in[n][4*s + k] * w[k] )
// N=1024, L=8192, KERNEL=16, STRIDE=4 -> OUTW = (L-16)/4 + 1 = 2045
//
// Decomposition: window s covers float4 indices u = s+d (d=0..3):
//   g_d(u) = min_c in4[u].c * w[4d+c];  out[s] = min_d g_d(s+d)
// Group i (32 outputs) needs g0(v[i]) and g1/g2/g3 of v[i] and v[i+1].
//
// Round-16: maximum-depth front batch. 4 warps x 512 outputs = full row
// per CTA (grid 1024, one balanced wave). Each warp issues ALL 17 float4
// loads in one branch-free burst (MLP=17, 8.7KB in flight per warp),
// then computes the 16 groups sequentially, carrying only the shared
// vector's g1/g2/g3 across groups so the g-arrays never inflate the
// register file. Packed mul.rn.f32x2 + source-side-select single-shuffle
// assembly (unchanged from the 8.6us kernels).

#define ROW_L4   2048
#define OUTW     2045
#define TPB      128
#define GROUPS   16
#define WARP_OUT (32 * GROUPS)            // 512 outputs per warp

typedef unsigned long long u64;

__device__ __forceinline__ u64 pk2(float a, float b) {
    u64 r; asm("mov.b64 %0, {%1, %2};" : "=l"(r) : "f"(a), "f"(b)); return r;
}
__device__ __forceinline__ u64 mul2(u64 a, u64 b) {
    u64 r; asm("mul.rn.f32x2 %0, %1, %2;" : "=l"(r) : "l"(a), "l"(b)); return r;
}
__device__ __forceinline__ float2 upk2(u64 p) {
    float x, y; asm("mov.b64 {%0, %1}, %2;" : "=f"(x), "=f"(y) : "l"(p));
    return make_float2(x, y);
}
// min over 4 components of v*w, v/w pre-packed as (lo=xy, hi=zw)
__device__ __forceinline__ float min4w_p(u64 vlo, u64 vhi, u64 wlo, u64 whi) {
    float2 a = upk2(mul2(vlo, wlo));
    float2 b = upk2(mul2(vhi, whi));
    return fminf(fminf(a.x, b.x), fminf(a.y, b.y));
}

__global__ __launch_bounds__(TPB)
void and_conv_kernel(const float4* __restrict__ in,
                     const float*  __restrict__ w,
                     float*        __restrict__ out)
{
    const int row  = blockIdx.x;
    const int warp = threadIdx.x >> 5;
    const int lane = threadIdx.x & 31;
    const int wbase = warp * WARP_OUT;            // warp's first output/float4

    const float4* __restrict__ rowp = in + (size_t)row * ROW_L4;
    float* __restrict__ orow = out + (size_t)row * OUTW;

    // ---- Phase 1: ALL loads in one branch-free burst (MLP = 17) ----
    float4 v[GROUPS + 1];
#pragma unroll
    for (int i = 0; i < GROUPS; ++i)
        v[i] = __ldg(&rowp[wbase + 32 * i + lane]);   // in-bounds (max 2047)
    v[GROUPS] = make_float4(0.f, 0.f, 0.f, 0.f);
    if (lane < 3) {                                   // halo: only lanes 0-2
        int idx = wbase + 32 * GROUPS + lane;         // warp3: clamp at end
        v[GROUPS] = __ldg(&rowp[idx < ROW_L4 - 1 ? idx : ROW_L4 - 1]);
    }

    // Weights, packed into f32x2 pairs (uniform -> broadcast, reg-resident)
    const float4* __restrict__ w4 = reinterpret_cast<const float4*>(w);
    u64 wlo[4], whi[4];
#pragma unroll
    for (int d = 0; d < 4; ++d) {
        float4 wd = __ldg(&w4[d]);
        wlo[d] = pk2(wd.x, wd.y);
        whi[d] = pk2(wd.z, wd.w);
    }

    // ---- Phase 2+3: per-group compute; carry shared vector's partials ----
    const unsigned F = 0xFFFFFFFFu;
    u64 clo = pk2(v[0].x, v[0].y), chi = pk2(v[0].z, v[0].w);
    float g1c = min4w_p(clo, chi, wlo[1], whi[1]);
    float g2c = min4w_p(clo, chi, wlo[2], whi[2]);
    float g3c = min4w_p(clo, chi, wlo[3], whi[3]);

#pragma unroll
    for (int i = 0; i < GROUPS; ++i) {
        const u64 ilo = pk2(v[i].x, v[i].y);
        const u64 ihi = pk2(v[i].z, v[i].w);
        const float g0 = min4w_p(ilo, ihi, wlo[0], whi[0]);

        const u64 nlo = pk2(v[i + 1].x, v[i + 1].y);
        const u64 nhi = pk2(v[i + 1].z, v[i + 1].w);
        const float g1n = min4w_p(nlo, nhi, wlo[1], whi[1]);
        const float g2n = min4w_p(nlo, nhi, wlo[2], whi[2]);
        const float g3n = min4w_p(nlo, nhi, wlo[3], whi[3]);

        // Wrapped readers (dest lane >= 32-d) hit src lanes 0..d-1, which
        // pre-select the NEXT vector's partial. Only lanes 0-2 ever export
        // halo-derived values, so lane>=3 halo zeros never propagate.
        float t1 = (lane < 1) ? g1n : g1c;
        float t2 = (lane < 2) ? g2n : g2c;
        float t3 = (lane < 3) ? g3n : g3c;
        float n1 = __shfl_sync(F, t1, (lane + 1) & 31);
        float n2 = __shfl_sync(F, t2, (lane + 2) & 31);
        float n3 = __shfl_sync(F, t3, (lane + 3) & 31);

        float r = fminf(fminf(g0, n1), fminf(n2, n3));

        int s = wbase + 32 * i + lane;
        if (s < OUTW) orow[s] = r;

        g1c = g1n; g2c = g2n; g3c = g3n;          // rotate carried partials
    }
}

extern "C" void kernel_launch(void* const* d_in, const int* in_sizes, int n_in,
                              void* d_out, int out_size)
{
    const float* inp = (const float*)d_in[0];   // (N, 8192) fp32
    const float* w   = (const float*)d_in[1];   // (1, 16)   fp32

    const int N = in_sizes[0] / 8192;           // 1024

    and_conv_kernel<<<N, TPB>>>(
        reinterpret_cast<const float4*>(inp), w, (float*)d_out);
}

// round 17
// speedup vs baseline: 1.0180x; 1.0180x over previous
#include <cuda_runtime.h>
#include <cstdint>
#include <float.h>

// And_Convolution: out[n][s] = min_{k<16} ( in[n][4*s + k] * w[k] )
// N=1024, L=8192, KERNEL=16, STRIDE=4 -> OUTW = (L-16)/4 + 1 = 2045
//
// Decomposition: window s covers float4 indices u = s+d (d=0..3):
//   g_d(u) = min_c in4[u].c * w[4d+c];  out[s] = min_d g_d(s+d)
//
// Round-17: hybrid depth. Warp owns 512 outputs (full row per CTA,
// grid 1024 = one balanced wave). Front batch = 9 LDG.128 (vectors 0-8,
// registers: the max ptxas will keep live, proven in R7) + 8 cp.async
// (vectors 9-16 -> smem: zero register cost, so the allocator CANNOT
// serialize them). Compute groups 0-7 from regs, wait_group, read
// vectors 9-16 via LDS (own-lane slots only -> no barrier), compute
// groups 8-15. Total committed depth ~17, register footprint ~R7.

#define ROW_L4   2048
#define OUTW     2045
#define TPB      128
#define HG       8                        // groups per half
#define WARP_OUT 512                      // outputs per warp

typedef unsigned long long u64;

__device__ __forceinline__ u64 pk2(float a, float b) {
    u64 r; asm("mov.b64 %0, {%1, %2};" : "=l"(r) : "f"(a), "f"(b)); return r;
}
__device__ __forceinline__ u64 mul2(u64 a, u64 b) {
    u64 r; asm("mul.rn.f32x2 %0, %1, %2;" : "=l"(r) : "l"(a), "l"(b)); return r;
}
__device__ __forceinline__ float2 upk2(u64 p) {
    float x, y; asm("mov.b64 {%0, %1}, %2;" : "=f"(x), "=f"(y) : "l"(p));
    return make_float2(x, y);
}
__device__ __forceinline__ float min4w_p(u64 vlo, u64 vhi, u64 wlo, u64 whi) {
    float2 a = upk2(mul2(vlo, wlo));
    float2 b = upk2(mul2(vhi, whi));
    return fminf(fminf(a.x, b.x), fminf(a.y, b.y));
}

__device__ __forceinline__ void cp_async16(uint32_t saddr, const void* gptr) {
    asm volatile("cp.async.cg.shared.global [%0], [%1], 16;"
                 :: "r"(saddr), "l"(gptr) : "memory");
}

__global__ __launch_bounds__(TPB)
void and_conv_kernel(const float4* __restrict__ in,
                     const float*  __restrict__ w,
                     float*        __restrict__ out)
{
    // per-warp staging: vectors 9..16 (8 vectors x 32 lanes x 16B)
    __shared__ alignas(16) float4 sm[4][8][32];

    const int row  = blockIdx.x;
    const int warp = threadIdx.x >> 5;
    const int lane = threadIdx.x & 31;
    const int wbase = warp * WARP_OUT;            // warp's first output/float4

    const float4* __restrict__ rowp = in + (size_t)row * ROW_L4;
    float* __restrict__ orow = out + (size_t)row * OUTW;

    // ---- Front batch: 8 cp.async (no regs) + 9 LDG (regs) ----
#pragma unroll
    for (int j = 0; j < 7; ++j) {                 // vectors 9..15, in-bounds
        const int gi = wbase + 32 * (9 + j) + lane;
        cp_async16((uint32_t)__cvta_generic_to_shared(&sm[warp][j][lane]),
                   rowp + gi);
    }
    if (lane < 3) {                               // halo vector 16, lanes 0-2
        int gi = wbase + 32 * 16 + lane;
        gi = gi < ROW_L4 - 1 ? gi : ROW_L4 - 1;   // warp3: clamp (dead outputs)
        cp_async16((uint32_t)__cvta_generic_to_shared(&sm[warp][7][lane]),
                   rowp + gi);
    }
    asm volatile("cp.async.commit_group;" ::: "memory");

    float4 v[HG + 1];
#pragma unroll
    for (int i = 0; i <= HG; ++i)                 // vectors 0..8, in-bounds
        v[i] = __ldg(&rowp[wbase + 32 * i + lane]);

    // Weights, packed (uniform -> broadcast, reg-resident)
    const float4* __restrict__ w4 = reinterpret_cast<const float4*>(w);
    u64 wlo[4], whi[4];
#pragma unroll
    for (int d = 0; d < 4; ++d) {
        float4 wd = __ldg(&w4[d]);
        wlo[d] = pk2(wd.x, wd.y);
        whi[d] = pk2(wd.z, wd.w);
    }

    const unsigned F = 0xFFFFFFFFu;

    // ---- compute one half (8 groups) from v[0..8] ----
    auto compute_half = [&](const float4* vv, int base) {
        float g0[HG], g1[HG + 1], g2[HG + 1], g3[HG + 1];
#pragma unroll
        for (int i = 0; i <= HG; ++i) {
            const u64 vlo = pk2(vv[i].x, vv[i].y);
            const u64 vhi = pk2(vv[i].z, vv[i].w);
            if (i < HG) g0[i] = min4w_p(vlo, vhi, wlo[0], whi[0]);
            g1[i] = min4w_p(vlo, vhi, wlo[1], whi[1]);
            g2[i] = min4w_p(vlo, vhi, wlo[2], whi[2]);
            g3[i] = min4w_p(vlo, vhi, wlo[3], whi[3]);
        }
#pragma unroll
        for (int i = 0; i < HG; ++i) {
            // Wrapped readers (dest lane >= 32-d) pull from src lanes
            // 0..d-1, which pre-select group i+1's partial.
            float t1 = (lane < 1) ? g1[i + 1] : g1[i];
            float t2 = (lane < 2) ? g2[i + 1] : g2[i];
            float t3 = (lane < 3) ? g3[i + 1] : g3[i];
            float n1 = __shfl_sync(F, t1, (lane + 1) & 31);
            float n2 = __shfl_sync(F, t2, (lane + 2) & 31);
            float n3 = __shfl_sync(F, t3, (lane + 3) & 31);

            float r = fminf(fminf(g0[i], n1), fminf(n2, n3));

            int s = base + 32 * i + lane;
            if (s < OUTW) orow[s] = r;
        }
    };

    // First half: groups 0..7 (cp.async flies underneath)
    compute_half(v, wbase);

    // ---- second half: vector 8 reused from regs, 9..16 from smem ----
    asm volatile("cp.async.wait_group 0;" ::: "memory");

    float4 v2[HG + 1];
    v2[0] = v[HG];                                // vector 8, still in regs
#pragma unroll
    for (int j = 0; j < 7; ++j)                   // vectors 9..15
        v2[1 + j] = sm[warp][j][lane];
    v2[HG] = make_float4(0.f, 0.f, 0.f, 0.f);     // halo: lanes 0-2 only
    if (lane < 3) v2[HG] = sm[warp][7][lane];

    compute_half(v2, wbase + 32 * HG);            // groups 8..15
}

extern "C" void kernel_launch(void* const* d_in, const int* in_sizes, int n_in,
                              void* d_out, int out_size)
{
    const float* inp = (const float*)d_in[0];   // (N, 8192) fp32
    const float* w   = (const float*)d_in[1];   // (1, 16)   fp32

    const int N = in_sizes[0] / 8192;           // 1024

    and_conv_kernel<<<N, TPB>>>(
        reinterpret_cast<const float4*>(inp), w, (float*)d_out);
}